// round 13
// baseline (speedup 1.0000x reference)
#include <cuda_runtime.h>
#include <cuda_bf16.h>
#include <cstdint>

#define NB 32
#define TT1 2048
#define TT2 512

// ---- scratch ----
__device__ __nv_bfloat16 g_A1k[1024ull*1536];
__device__ __nv_bfloat16 g_A2k[128ull*1024];
__device__ __nv_bfloat16 g_A1q[224ull*320];
__device__ __nv_bfloat16 g_A2q[128ull*224];
__device__ __nv_bfloat16 g_A3q[128ull*128];
__device__ __nv_bfloat16 g_Bk1[(size_t)NB*1536*512];
__device__ __nv_bfloat16 g_Bq1[(size_t)NB*320*2048];
__device__ __nv_bfloat16 g_Hk [(size_t)NB*1024*512];
__device__ __nv_bfloat16 g_Kb [(size_t)NB*128*512];
__device__ __nv_bfloat16 g_Hq1[(size_t)NB*224*2048];
__device__ __nv_bfloat16 g_Hq2[(size_t)NB*128*2048];
__device__ __nv_bfloat16 g_QT [(size_t)NB*2048*128];
__device__ float g_q2[NB*TT1];
__device__ float g_k2[NB*TT2];

// ---- ptx helpers ----
__device__ __forceinline__ void cp16(uint32_t dst, const void* src, int sz){
    asm volatile("cp.async.cg.shared.global [%0], [%1], 16, %2;\n"::"r"(dst),"l"(src),"r"(sz):"memory");
}
__device__ __forceinline__ void cpcommit(){ asm volatile("cp.async.commit_group;\n":::"memory"); }
__device__ __forceinline__ void cpwait0(){ asm volatile("cp.async.wait_group 0;\n":::"memory"); }
__device__ __forceinline__ void cpwait1(){ asm volatile("cp.async.wait_group 1;\n":::"memory"); }
__device__ __forceinline__ void cpwait2(){ asm volatile("cp.async.wait_group 2;\n":::"memory"); }
__device__ __forceinline__ void ldsm4(uint32_t&r0,uint32_t&r1,uint32_t&r2,uint32_t&r3,uint32_t a){
    asm volatile("ldmatrix.sync.aligned.m8n8.x4.shared.b16 {%0,%1,%2,%3},[%4];"
        :"=r"(r0),"=r"(r1),"=r"(r2),"=r"(r3):"r"(a));
}
__device__ __forceinline__ void ldsm4t(uint32_t&r0,uint32_t&r1,uint32_t&r2,uint32_t&r3,uint32_t a){
    asm volatile("ldmatrix.sync.aligned.m8n8.x4.trans.shared.b16 {%0,%1,%2,%3},[%4];"
        :"=r"(r0),"=r"(r1),"=r"(r2),"=r"(r3):"r"(a));
}
__device__ __forceinline__ void mma16816(float*c,const uint32_t*a,const uint32_t*b){
    asm volatile("mma.sync.aligned.m16n8k16.row.col.f32.bf16.bf16.f32 "
        "{%0,%1,%2,%3},{%4,%5,%6,%7},{%8,%9},{%0,%1,%2,%3};"
        :"+f"(c[0]),"+f"(c[1]),"+f"(c[2]),"+f"(c[3])
        :"r"(a[0]),"r"(a[1]),"r"(a[2]),"r"(a[3]),"r"(b[0]),"r"(b[1]));
}

// ---- vectorized weight pack ----
__global__ void pack_w8(const float* __restrict__ W, __nv_bfloat16* __restrict__ dst,
                        int Cout,int Cin,int KW,int Kpad,int Mpad){
    int idx = blockIdx.x*256+threadIdx.x;
    int K8 = Kpad>>3;
    if (idx >= Mpad*K8) return;
    int co = idx/K8, k0 = (idx - co*K8)<<3;
    __nv_bfloat16 v[8];
#pragma unroll
    for (int u=0;u<8;u++){
        int k = k0+u; float f = 0.f;
        if (co < Cout && k < Cin*KW){ int j=k/Cin, ci=k-j*Cin; f = W[(co*Cin+ci)*KW+j]; }
        v[u] = __float2bfloat16(f);
    }
    *reinterpret_cast<uint4*>(dst + (size_t)co*Kpad + k0) = *reinterpret_cast<const uint4*>(v);
}

// ---- vectorized im2col [k][t] ----
__global__ void im2col_v8(const float* __restrict__ X, __nv_bfloat16* __restrict__ dst,
                          int C,int T,int Kpad){
    int b = blockIdx.z;
    int idx = blockIdx.x*256+threadIdx.x;
    int T8 = T>>3;
    if (idx >= Kpad*T8) return;
    int k = idx/T8, t8 = (idx - k*T8)<<3;
    __nv_bfloat16 v[8];
    if (k < 3*C){
        int j = k/C, ci = k - j*C;
        const float* src = X + ((size_t)b*C+ci)*T;
        int tb = t8 + j - 1;
#pragma unroll
        for (int u=0;u<8;u++){
            int tt = tb+u;
            v[u] = __float2bfloat16((tt>=0 && tt<T) ? src[tt] : 0.f);
        }
    } else {
#pragma unroll
        for (int u=0;u<8;u++) v[u] = __float2bfloat16(0.f);
    }
    *reinterpret_cast<uint4*>(dst + ((size_t)b*Kpad + k)*T + t8) = *reinterpret_cast<const uint4*>(v);
}

// ---- shared GEMM tile constants (R11 proven config) ----
#define BM 128
#define BN 128
#define BKT 32
#define AST 40
#define BST 136
#define NSTG 4
#define GSMEM (NSTG*(BM*AST + BKT*BST)*2)

// ======== 128-thread GEMM (4 warps, 64x64 warp tiles) — GEMM1 ========
template <bool RELU>
__global__ void __launch_bounds__(128,2)
gemm128(const __nv_bfloat16* __restrict__ A, size_t aBatch, int lda,
        const __nv_bfloat16* __restrict__ Bm, size_t bBatch, int ldb,
        __nv_bfloat16* __restrict__ Cv, size_t cBatch, int ldc,
        const float* __restrict__ bias, int M, int Kpad, int Mstore){
    extern __shared__ char dsm[];
    __nv_bfloat16* sA = (__nv_bfloat16*)dsm;
    __nv_bfloat16* sB = sA + NSTG*BM*AST;
    const int bz = blockIdx.z;
    A  += (size_t)bz*aBatch;
    Bm += (size_t)bz*bBatch;
    const int m0 = blockIdx.y*BM, n0 = blockIdx.x*BN;
    const int tid = threadIdx.x, lane = tid&31, wid = tid>>5;
    const int wm = wid&1, wn = wid>>1;
    const uint32_t saA = (uint32_t)__cvta_generic_to_shared(sA);
    const uint32_t sbA = (uint32_t)__cvta_generic_to_shared(sB);

    float acc[4][8][4];
#pragma unroll
    for (int i=0;i<4;i++)
#pragma unroll
        for (int j=0;j<8;j++)
#pragma unroll
            for (int q=0;q<4;q++) acc[i][j][q]=0.f;

    const int KT = Kpad/BKT;
    auto loadTiles = [&](int kt,int s){
        int k0 = kt*BKT;
        uint32_t sa = saA + s*(BM*AST*2);
        uint32_t sb = sbA + s*(BKT*BST*2);
#pragma unroll
        for (int i=0;i<4;i++){
            int c = tid+128*i, row = c>>2, cc = (c&3)*8;
            cp16(sa + (row*AST+cc)*2, A + (size_t)(m0+row)*lda + k0 + cc, 16);
        }
#pragma unroll
        for (int i=0;i<4;i++){
            int c = tid+128*i, row = c>>4, cc = (c&15)*8;
            cp16(sb + (row*BST+cc)*2, Bm + (size_t)(k0+row)*ldb + n0 + cc, 16);
        }
    };

    loadTiles(0,0); cpcommit();
    loadTiles(1,1); cpcommit();
    loadTiles(2,2); cpcommit();
    for (int kt=0; kt<KT; kt++){
        int s = kt & 3;
        if (kt >= KT-2) cpwait0(); else cpwait2();
        __syncthreads();
        if (kt+3 < KT){ loadTiles(kt+3, (kt+3)&3); cpcommit(); }
        uint32_t sa = saA + s*(BM*AST*2);
        uint32_t sb = sbA + s*(BKT*BST*2);
#pragma unroll
        for (int ks=0; ks<2; ks++){
            int kk = ks*16;
            uint32_t af[4][4];
#pragma unroll
            for (int i=0;i<4;i++){
                int row = wm*64 + i*16 + (lane&15);
                int col = kk + ((lane>>4)<<3);
                ldsm4(af[i][0],af[i][1],af[i][2],af[i][3], sa + (row*AST+col)*2);
            }
            uint32_t bfr[8][2];
#pragma unroll
            for (int p=0;p<4;p++){
                int row = kk + (lane&15);
                int col = wn*64 + p*16 + ((lane>>4)<<3);
                uint32_t r0,r1,r2,r3;
                ldsm4t(r0,r1,r2,r3, sb + (row*BST+col)*2);
                bfr[2*p][0]=r0; bfr[2*p][1]=r1; bfr[2*p+1][0]=r2; bfr[2*p+1][1]=r3;
            }
#pragma unroll
            for (int i=0;i<4;i++)
#pragma unroll
                for (int j=0;j<8;j++) mma16816(acc[i][j], af[i], bfr[j]);
        }
    }

    const int g = lane>>2, tg = lane&3;
    const size_t cOff = (size_t)bz*cBatch;
#pragma unroll
    for (int i=0;i<4;i++)
#pragma unroll
        for (int j=0;j<8;j++){
            int col = n0 + wn*64 + j*8 + tg*2;
#pragma unroll
            for (int h=0;h<2;h++){
                int r = m0 + wm*64 + i*16 + g + h*8;
                if (r < Mstore){
                    float v0 = acc[i][j][h*2], v1 = acc[i][j][h*2+1];
                    if (r < M){
                        if (bias){ float bb = bias[r]; v0+=bb; v1+=bb; }
                        if (RELU){ v0=fmaxf(v0,0.f); v1=fmaxf(v1,0.f); }
                    } else { v0=0.f; v1=0.f; }
                    __nv_bfloat162 pv; pv.x=__float2bfloat16(v0); pv.y=__float2bfloat16(v1);
                    *reinterpret_cast<__nv_bfloat162*>(Cv + cOff + (size_t)r*ldc + col) = pv;
                }
            }
        }
}

// ======== 256-thread GEMM (8 warps, 32x64 warp tiles) — small layers ========
template <bool RELU, bool TRANSQ>
__global__ void __launch_bounds__(256,2)
gemm256(const __nv_bfloat16* __restrict__ A, size_t aBatch, int lda,
        const __nv_bfloat16* __restrict__ Bm, size_t bBatch, int ldb,
        __nv_bfloat16* __restrict__ Cv, size_t cBatch, int ldc,
        const float* __restrict__ bias, int M, int Kpad, int Mstore,
        float* __restrict__ q2out){
    extern __shared__ char dsm[];
    __nv_bfloat16* sA = (__nv_bfloat16*)dsm;
    __nv_bfloat16* sB = sA + NSTG*BM*AST;
    const int bz = blockIdx.z;
    A  += (size_t)bz*aBatch;
    Bm += (size_t)bz*bBatch;
    const int m0 = blockIdx.y*BM, n0 = blockIdx.x*BN;
    const int tid = threadIdx.x, lane = tid&31, wid = tid>>5;
    const int wm = wid&3, wn = wid>>2;
    const uint32_t saA = (uint32_t)__cvta_generic_to_shared(sA);
    const uint32_t sbA = (uint32_t)__cvta_generic_to_shared(sB);

    float acc[2][8][4];
#pragma unroll
    for (int i=0;i<2;i++)
#pragma unroll
        for (int j=0;j<8;j++){acc[i][j][0]=0;acc[i][j][1]=0;acc[i][j][2]=0;acc[i][j][3]=0;}

    const int KT = Kpad/BKT;
    auto loadTiles = [&](int kt,int s){
        int k0 = kt*BKT;
        uint32_t sa = saA + s*(BM*AST*2);
        uint32_t sb = sbA + s*(BKT*BST*2);
#pragma unroll
        for (int i=0;i<2;i++){
            int c = tid+256*i, row = c>>2, cc = (c&3)*8;
            cp16(sa + (row*AST+cc)*2, A + (size_t)(m0+row)*lda + k0 + cc, 16);
        }
#pragma unroll
        for (int i=0;i<2;i++){
            int c = tid+256*i, row = c>>4, cc = (c&15)*8;
            cp16(sb + (row*BST+cc)*2, Bm + (size_t)(k0+row)*ldb + n0 + cc, 16);
        }
    };

    loadTiles(0,0); cpcommit();
    loadTiles(1,1); cpcommit();
    loadTiles(2,2); cpcommit();
    for (int kt=0; kt<KT; kt++){
        int s = kt & 3;
        if (kt >= KT-2) cpwait0(); else cpwait2();
        __syncthreads();
        if (kt+3 < KT){ loadTiles(kt+3, (kt+3)&3); cpcommit(); }
        uint32_t sa = saA + s*(BM*AST*2);
        uint32_t sb = sbA + s*(BKT*BST*2);
#pragma unroll
        for (int ks=0; ks<2; ks++){
            int kk = ks*16;
            uint32_t af[2][4];
#pragma unroll
            for (int i=0;i<2;i++){
                int row = wm*32 + i*16 + (lane&15);
                int col = kk + ((lane>>4)<<3);
                ldsm4(af[i][0],af[i][1],af[i][2],af[i][3], sa + (row*AST+col)*2);
            }
            uint32_t bfr[8][2];
#pragma unroll
            for (int p=0;p<4;p++){
                int row = kk + (lane&15);
                int col = wn*64 + p*16 + ((lane>>4)<<3);
                uint32_t r0,r1,r2,r3;
                ldsm4t(r0,r1,r2,r3, sb + (row*BST+col)*2);
                bfr[2*p][0]=r0; bfr[2*p][1]=r1; bfr[2*p+1][0]=r2; bfr[2*p+1][1]=r3;
            }
#pragma unroll
            for (int i=0;i<2;i++)
#pragma unroll
                for (int j=0;j<8;j++) mma16816(acc[i][j], af[i], bfr[j]);
        }
    }

    const int g = lane>>2, tg = lane&3;
    if (TRANSQ){
        __syncthreads();
        __nv_bfloat16* sT = (__nv_bfloat16*)dsm;
#pragma unroll
        for (int i=0;i<2;i++)
#pragma unroll
            for (int j=0;j<8;j++){
                int colb = wn*64 + j*8 + tg*2;
#pragma unroll
                for (int q=0;q<4;q++){
                    int h=q>>1, s=q&1;
                    int r = wm*32 + i*16 + g + h*8;
                    float v = acc[i][j][q];
                    if (r < M) v += bias[r]; else v = 0.f;
                    sT[(colb+s)*136 + r] = __float2bfloat16(v);
                }
            }
        __syncthreads();
        if (tid < 128){
            int row = tid;
            size_t t = (size_t)n0 + row;
            const uint4* src = (const uint4*)(sT + row*136);
            uint4* dstp = (uint4*)(Cv + (size_t)bz*cBatch + t*128);
            float ssum = 0.f;
#pragma unroll
            for (int u=0;u<16;u++){
                uint4 w = src[u];
                dstp[u] = w;
                const uint32_t wv[4] = {w.x,w.y,w.z,w.w};
#pragma unroll
                for (int e=0;e<4;e++){
                    float2 f2 = __bfloat1622float2(*reinterpret_cast<const __nv_bfloat162*>(&wv[e]));
                    ssum += f2.x*f2.x + f2.y*f2.y;
                }
            }
            q2out[bz*TT1 + t] = ssum;
        }
        return;
    }

    const size_t cOff = (size_t)bz*cBatch;
#pragma unroll
    for (int i=0;i<2;i++)
#pragma unroll
        for (int j=0;j<8;j++){
            int col = n0 + wn*64 + j*8 + tg*2;
#pragma unroll
            for (int h=0;h<2;h++){
                int r = m0 + wm*32 + i*16 + g + h*8;
                if (r < Mstore){
                    float v0 = acc[i][j][h*2], v1 = acc[i][j][h*2+1];
                    if (r < M){
                        if (bias){ float bb = bias[r]; v0+=bb; v1+=bb; }
                        if (RELU){ v0=fmaxf(v0,0.f); v1=fmaxf(v1,0.f); }
                    } else { v0=0.f; v1=0.f; }
                    __nv_bfloat162 pv; pv.x=__float2bfloat16(v0); pv.y=__float2bfloat16(v1);
                    *reinterpret_cast<__nv_bfloat162*>(Cv + cOff + (size_t)r*ldc + col) = pv;
                }
            }
        }
}

// ---- channel sum-of-squares (K path) ----
__global__ void sumsq_kernel(const __nv_bfloat16* __restrict__ X, float* __restrict__ out,
                             int C,int T,size_t bStride){
    int b = blockIdx.y, t = blockIdx.x*256+threadIdx.x;
    if (t >= T) return;
    const __nv_bfloat16* p = X + (size_t)b*bStride + t;
    float s = 0.f;
    for (int c=0;c<C;c++){ float v = __bfloat162float(p[(size_t)c*T]); s += v*v; }
    out[b*T+t] = s;
}

// ---- persistent fused qk + attention ----
// grid (4, NB): each CTA keeps full K resident, loops over 8 Q-tiles of 64 rows.
#define KROWS 128
#define KST 520
#define QROWS 64
#define QST 136
#define AGX 4
#define ATILES (TT1/(QROWS*AGX))   // 8
#define ATTN_SMEM (KROWS*KST*2 + 2*QROWS*QST*2 + 512*4 + 512*4 + QROWS*8*4)

template<bool MAXOP>
__device__ __forceinline__ void rowReduce64(float val[2][2], float* sred, int wm,int g,int tg,int wn){
#pragma unroll
    for (int i=0;i<2;i++)
#pragma unroll
        for (int h=0;h<2;h++){
            float v = val[i][h];
            float o = __shfl_xor_sync(0xffffffffu, v, 1);
            v = MAXOP ? fmaxf(v,o) : v+o;
            o = __shfl_xor_sync(0xffffffffu, v, 2);
            v = MAXOP ? fmaxf(v,o) : v+o;
            if (tg==0) sred[(wm*32 + i*16+g+h*8)*8+wn] = v;
        }
    __syncthreads();
#pragma unroll
    for (int i=0;i<2;i++)
#pragma unroll
        for (int h=0;h<2;h++){
            int r = wm*32 + i*16+g+h*8;
            float v = sred[r*8];
#pragma unroll
            for (int w=1;w<8;w++) v = MAXOP ? fmaxf(v,sred[r*8+w]) : v+sred[r*8+w];
            val[i][h]=v;
        }
    __syncthreads();
}

__global__ void __launch_bounds__(512,1)
qk_attn(const __nv_bfloat16* __restrict__ QT, const __nv_bfloat16* __restrict__ Kb,
        const float* __restrict__ q2, const float* __restrict__ k2,
        const float* __restrict__ prior, const int* __restrict__ mask,
        float* __restrict__ outA, float* __restrict__ outLP){
    extern __shared__ char sm[];
    __nv_bfloat16* sK = (__nv_bfloat16*)sm;
    __nv_bfloat16* sQ = sK + KROWS*KST;
    float* sk2  = (float*)(sQ + 2*QROWS*QST);
    int*  smask = (int*)(sk2 + 512);
    float* sred = (float*)(smask + 512);

    const int b = blockIdx.y;
    const int tid = threadIdx.x, lane = tid&31, wid = tid>>5;
    const int wm = wid>>3, wn = wid&7;
    const int g = lane>>2, tg = lane&3;
    const __nv_bfloat16* Kg = Kb + (size_t)b*128*512;
    const uint32_t sKa = (uint32_t)__cvta_generic_to_shared(sK);
    const uint32_t sQa = (uint32_t)__cvta_generic_to_shared(sQ);
    const int tileBase = blockIdx.x*ATILES;

    // K full (128x512) + Q tile 0 in one group
#pragma unroll
    for (int i=0;i<16;i++){
        int c = tid + 512*i, row = c>>6, cc = (c&63)*8;
        cp16(sKa + (row*KST+cc)*2, Kg + (size_t)row*512 + cc, 16);
    }
    {
        const __nv_bfloat16* Qg = QT + ((size_t)b*TT1 + tileBase*QROWS)*128;
#pragma unroll
        for (int i=0;i<2;i++){
            int c = tid + 512*i, row = c>>4, cc = (c&15)*8;
            cp16(sQa + (row*QST+cc)*2, Qg + (size_t)row*128 + cc, 16);
        }
    }
    cpcommit();
    sk2[tid]   = k2[b*TT2 + tid];
    smask[tid] = mask[b*TT2 + tid];

    for (int t=0; t<ATILES; t++){
        int m0 = (tileBase + t)*QROWS;
        cpwait0(); __syncthreads();
        uint32_t qbuf = sQa + (t&1)*(QROWS*QST*2);
        if (t+1 < ATILES){
            const __nv_bfloat16* Qg = QT + ((size_t)b*TT1 + m0 + QROWS)*128;
            uint32_t qb2 = sQa + ((t+1)&1)*(QROWS*QST*2);
#pragma unroll
            for (int i=0;i<2;i++){
                int c = tid + 512*i, row = c>>4, cc = (c&15)*8;
                cp16(qb2 + (row*QST+cc)*2, Qg + (size_t)row*128 + cc, 16);
            }
            cpcommit();
        }

        float acc[2][8][4];
#pragma unroll
        for (int i=0;i<2;i++)
#pragma unroll
            for (int j=0;j<8;j++){acc[i][j][0]=0;acc[i][j][1]=0;acc[i][j][2]=0;acc[i][j][3]=0;}

#pragma unroll
        for (int ks=0; ks<8; ks++){
            int kk = ks*16;
            uint32_t af[2][4];
#pragma unroll
            for (int i=0;i<2;i++){
                int row = wm*32 + i*16 + (lane&15);
                int col = kk + ((lane>>4)<<3);
                ldsm4(af[i][0],af[i][1],af[i][2],af[i][3], qbuf + (row*QST+col)*2);
            }
            uint32_t bfr[8][2];
#pragma unroll
            for (int p=0;p<4;p++){
                int row = kk + (lane&15);
                int col = wn*64 + p*16 + ((lane>>4)<<3);
                uint32_t r0,r1,r2,r3;
                ldsm4t(r0,r1,r2,r3, sKa + (row*KST+col)*2);
                bfr[2*p][0]=r0; bfr[2*p][1]=r1; bfr[2*p+1][0]=r2; bfr[2*p+1][1]=r3;
            }
#pragma unroll
            for (int i=0;i<2;i++)
#pragma unroll
                for (int j=0;j<8;j++) mma16816(acc[i][j], af[i], bfr[j]);
        }

        const size_t rowBase = (size_t)b*TT1 + m0;
        float q2v[2][2];
#pragma unroll
        for (int i=0;i<2;i++)
#pragma unroll
            for (int h=0;h<2;h++) q2v[i][h] = q2[rowBase + wm*32 + i*16+g+h*8];

#pragma unroll
        for (int i=0;i<2;i++)
#pragma unroll
            for (int j=0;j<8;j++)
#pragma unroll
                for (int q=0;q<4;q++){
                    int h = q>>1, s = q&1;
                    int col = wn*64 + j*8 + tg*2 + s;
                    acc[i][j][q] = -5e-4f*(q2v[i][h] + sk2[col] - 2.f*acc[i][j][q]);
                }

        float mx[2][2] = {{-1e30f,-1e30f},{-1e30f,-1e30f}};
#pragma unroll
        for (int i=0;i<2;i++)
#pragma unroll
            for (int j=0;j<8;j++)
#pragma unroll
                for (int q=0;q<4;q++){ int h=q>>1; mx[i][h] = fmaxf(mx[i][h], acc[i][j][q]); }
        rowReduce64<true>(mx, sred, wm, g, tg, wn);
        float sme[2][2] = {{0,0},{0,0}};
#pragma unroll
        for (int i=0;i<2;i++)
#pragma unroll
            for (int j=0;j<8;j++)
#pragma unroll
                for (int q=0;q<4;q++){ int h=q>>1; sme[i][h] += __expf(acc[i][j][q]-mx[i][h]); }
        rowReduce64<false>(sme, sred, wm, g, tg, wn);
        float lse[2][2];
#pragma unroll
        for (int i=0;i<2;i++)
#pragma unroll
            for (int h=0;h<2;h++) lse[i][h] = mx[i][h] + __logf(sme[i][h]);

        float s2[2][2] = {{0,0},{0,0}};
#pragma unroll
        for (int i=0;i<2;i++)
#pragma unroll
            for (int j=0;j<8;j++)
#pragma unroll
                for (int q=0;q<4;q++){
                    int h=q>>1, s=q&1;
                    int r = wm*32 + i*16+g+h*8, col = wn*64 + j*8 + tg*2 + s;
                    size_t off = (rowBase + r)*TT2 + col;
                    float lp = acc[i][j][q] - lse[i][h] + __logf(prior[off] + 1e-8f);
                    outLP[off] = lp;
                    float e = smask[col] ? 0.f : __expf(lp);
                    acc[i][j][q] = e;
                    s2[i][h] += e;
                }
        rowReduce64<false>(s2, sred, wm, g, tg, wn);
#pragma unroll
        for (int i=0;i<2;i++)
#pragma unroll
            for (int j=0;j<8;j++)
#pragma unroll
                for (int q=0;q<4;q++){
                    int h=q>>1, s=q&1;
                    int r = wm*32 + i*16+g+h*8, col = wn*64 + j*8 + tg*2 + s;
                    size_t off = (rowBase + r)*TT2 + col;
                    float inv = s2[i][h] > 0.f ? 1.f/s2[i][h] : 0.f;
                    outA[off] = acc[i][j][q]*inv;
                }
    }
}

extern "C" void kernel_launch(void* const* d_in, const int* in_sizes, int n_in,
                              void* d_out, int out_size){
    (void)in_sizes; (void)n_in; (void)out_size;
    const float* queries = (const float*)d_in[0];
    const float* keys    = (const float*)d_in[1];
    const int*   mask    = (const int*)d_in[3];
    const float* prior   = (const float*)d_in[4];
    const float* kW1=(const float*)d_in[5];  const float* kb1=(const float*)d_in[6];
    const float* kW2=(const float*)d_in[7];  const float* kb2=(const float*)d_in[8];
    const float* qW1=(const float*)d_in[9];  const float* qb1=(const float*)d_in[10];
    const float* qW2=(const float*)d_in[11]; const float* qb2=(const float*)d_in[12];
    const float* qW3=(const float*)d_in[13]; const float* qb3=(const float*)d_in[14];

    void *pA1k,*pA2k,*pA1q,*pA2q,*pA3q,*pBk1,*pBq1,*pHk,*pKb,*pHq1,*pHq2,*pQT,*pq2,*pk2;
    cudaGetSymbolAddress(&pA1k,g_A1k); cudaGetSymbolAddress(&pA2k,g_A2k);
    cudaGetSymbolAddress(&pA1q,g_A1q); cudaGetSymbolAddress(&pA2q,g_A2q);
    cudaGetSymbolAddress(&pA3q,g_A3q); cudaGetSymbolAddress(&pBk1,g_Bk1);
    cudaGetSymbolAddress(&pBq1,g_Bq1); cudaGetSymbolAddress(&pHk,g_Hk);
    cudaGetSymbolAddress(&pKb,g_Kb);   cudaGetSymbolAddress(&pHq1,g_Hq1);
    cudaGetSymbolAddress(&pHq2,g_Hq2); cudaGetSymbolAddress(&pQT,g_QT);
    cudaGetSymbolAddress(&pq2,g_q2);   cudaGetSymbolAddress(&pk2,g_k2);

    cudaFuncSetAttribute(gemm128<true>, cudaFuncAttributeMaxDynamicSharedMemorySize, GSMEM);
    cudaFuncSetAttribute(gemm256<false,false>, cudaFuncAttributeMaxDynamicSharedMemorySize, GSMEM);
    cudaFuncSetAttribute(gemm256<true,false>,  cudaFuncAttributeMaxDynamicSharedMemorySize, GSMEM);
    cudaFuncSetAttribute(gemm256<false,true>,  cudaFuncAttributeMaxDynamicSharedMemorySize, GSMEM);
    cudaFuncSetAttribute(qk_attn, cudaFuncAttributeMaxDynamicSharedMemorySize, ATTN_SMEM);

    static cudaStream_t s2 = nullptr;
    static cudaEvent_t eFork = nullptr, eJoin = nullptr;
    if (!s2){
        cudaStreamCreateWithFlags(&s2, cudaStreamNonBlocking);
        cudaEventCreateWithFlags(&eFork, cudaEventDisableTiming);
        cudaEventCreateWithFlags(&eJoin, cudaEventDisableTiming);
    }

    cudaEventRecord(eFork, 0);
    cudaStreamWaitEvent(s2, eFork, 0);

    // --- key path (default stream) ---
    im2col_v8<<<dim3((1536*512/8+255)/256,1,NB),256>>>(keys,(__nv_bfloat16*)pBk1,512,512,1536);
    pack_w8<<<(1024*1536/8+255)/256,256>>>(kW1,(__nv_bfloat16*)pA1k,1024,512,3,1536,1024);
    // --- query path starts on s2 ---
    im2col_v8<<<dim3((320*2048/8+255)/256,1,NB),256,0,s2>>>(queries,(__nv_bfloat16*)pBq1,100,2048,320);
    // launch index 3: dominant GEMM (ncu capture slot)
    gemm128<true><<<dim3(4,8,NB),128,GSMEM>>>(
        (const __nv_bfloat16*)pA1k,0,1536,(const __nv_bfloat16*)pBk1,(size_t)1536*512,512,
        (__nv_bfloat16*)pHk,(size_t)1024*512,512, kb1, 1024,1536,1024);
    pack_w8<<<(128*1024/8+255)/256,256>>>(kW2,(__nv_bfloat16*)pA2k,100,1024,1,1024,128);
    gemm256<false,false><<<dim3(4,1,NB),256,GSMEM>>>(
        (const __nv_bfloat16*)pA2k,0,1024,(const __nv_bfloat16*)pHk,(size_t)1024*512,512,
        (__nv_bfloat16*)pKb,(size_t)128*512,512, kb2, 100,1024,128, nullptr);
    sumsq_kernel<<<dim3(2,NB),256>>>((const __nv_bfloat16*)pKb,(float*)pk2,100,512,(size_t)128*512);

    // --- query path (s2) ---
    pack_w8<<<(224*320/8+255)/256,256,0,s2>>>(qW1,(__nv_bfloat16*)pA1q,200,100,3,320,224);
    pack_w8<<<(128*224/8+255)/256,256,0,s2>>>(qW2,(__nv_bfloat16*)pA2q,100,200,1,224,128);
    pack_w8<<<(128*128/8+255)/256,256,0,s2>>>(qW3,(__nv_bfloat16*)pA3q,100,100,1,128,128);
    gemm256<true,false><<<dim3(16,2,NB),256,GSMEM,s2>>>(
        (const __nv_bfloat16*)pA1q,0,320,(const __nv_bfloat16*)pBq1,(size_t)320*2048,2048,
        (__nv_bfloat16*)pHq1,(size_t)224*2048,2048, qb1, 200,320,224, nullptr);
    gemm256<true,false><<<dim3(16,1,NB),256,GSMEM,s2>>>(
        (const __nv_bfloat16*)pA2q,0,224,(const __nv_bfloat16*)pHq1,(size_t)224*2048,2048,
        (__nv_bfloat16*)pHq2,(size_t)128*2048,2048, qb2, 100,224,128, nullptr);
    gemm256<false,true><<<dim3(16,1,NB),256,GSMEM,s2>>>(
        (const __nv_bfloat16*)pA3q,0,128,(const __nv_bfloat16*)pHq2,(size_t)128*2048,2048,
        (__nv_bfloat16*)pQT,(size_t)2048*128,128, qb3, 100,128,128, (float*)pq2);
    cudaEventRecord(eJoin, s2);
    cudaStreamWaitEvent(0, eJoin, 0);

    // --- join: persistent fused qk + attention ---
    float* outA = (float*)d_out;
    float* outLP = outA + (size_t)NB*TT1*TT2;
    qk_attn<<<dim3(AGX,NB),512,ATTN_SMEM>>>(
        (const __nv_bfloat16*)pQT,(const __nv_bfloat16*)pKb,
        (const float*)pq2,(const float*)pk2, prior, mask, outA, outLP);
}

// round 14
// speedup vs baseline: 1.1156x; 1.1156x over previous
#include <cuda_runtime.h>
#include <cuda_bf16.h>
#include <cstdint>

#define NB 32
#define TT1 2048
#define TT2 512

// ---- scratch ----
__device__ __nv_bfloat16 g_A1k[1024ull*1536];
__device__ __nv_bfloat16 g_A2k[128ull*1024];
__device__ __nv_bfloat16 g_A1q[224ull*320];
__device__ __nv_bfloat16 g_A2q[128ull*224];
__device__ __nv_bfloat16 g_A3q[128ull*128];
__device__ __nv_bfloat16 g_Bk1[(size_t)NB*1536*512];
__device__ __nv_bfloat16 g_Bq1[(size_t)NB*320*2048];
__device__ __nv_bfloat16 g_Hk [(size_t)NB*1024*512];
__device__ __nv_bfloat16 g_Kb [(size_t)NB*128*512];
__device__ __nv_bfloat16 g_Hq1[(size_t)NB*224*2048];
__device__ __nv_bfloat16 g_Hq2[(size_t)NB*128*2048];
__device__ __nv_bfloat16 g_QT [(size_t)NB*2048*128];
__device__ float g_q2[NB*TT1];
__device__ float g_k2[NB*TT2];

// ---- ptx helpers ----
__device__ __forceinline__ void cp16(uint32_t dst, const void* src, int sz){
    asm volatile("cp.async.cg.shared.global [%0], [%1], 16, %2;\n"::"r"(dst),"l"(src),"r"(sz):"memory");
}
__device__ __forceinline__ void cpcommit(){ asm volatile("cp.async.commit_group;\n":::"memory"); }
__device__ __forceinline__ void cpwait0(){ asm volatile("cp.async.wait_group 0;\n":::"memory"); }
__device__ __forceinline__ void cpwait1(){ asm volatile("cp.async.wait_group 1;\n":::"memory"); }
__device__ __forceinline__ void cpwait2(){ asm volatile("cp.async.wait_group 2;\n":::"memory"); }
__device__ __forceinline__ void ldsm4(uint32_t&r0,uint32_t&r1,uint32_t&r2,uint32_t&r3,uint32_t a){
    asm volatile("ldmatrix.sync.aligned.m8n8.x4.shared.b16 {%0,%1,%2,%3},[%4];"
        :"=r"(r0),"=r"(r1),"=r"(r2),"=r"(r3):"r"(a));
}
__device__ __forceinline__ void ldsm4t(uint32_t&r0,uint32_t&r1,uint32_t&r2,uint32_t&r3,uint32_t a){
    asm volatile("ldmatrix.sync.aligned.m8n8.x4.trans.shared.b16 {%0,%1,%2,%3},[%4];"
        :"=r"(r0),"=r"(r1),"=r"(r2),"=r"(r3):"r"(a));
}
__device__ __forceinline__ void mma16816(float*c,const uint32_t*a,const uint32_t*b){
    asm volatile("mma.sync.aligned.m16n8k16.row.col.f32.bf16.bf16.f32 "
        "{%0,%1,%2,%3},{%4,%5,%6,%7},{%8,%9},{%0,%1,%2,%3};"
        :"+f"(c[0]),"+f"(c[1]),"+f"(c[2]),"+f"(c[3])
        :"r"(a[0]),"r"(a[1]),"r"(a[2]),"r"(a[3]),"r"(b[0]),"r"(b[1]));
}

// ---- vectorized weight pack ----
__global__ void pack_w8(const float* __restrict__ W, __nv_bfloat16* __restrict__ dst,
                        int Cout,int Cin,int KW,int Kpad,int Mpad){
    int idx = blockIdx.x*256+threadIdx.x;
    int K8 = Kpad>>3;
    if (idx >= Mpad*K8) return;
    int co = idx/K8, k0 = (idx - co*K8)<<3;
    __nv_bfloat16 v[8];
#pragma unroll
    for (int u=0;u<8;u++){
        int k = k0+u; float f = 0.f;
        if (co < Cout && k < Cin*KW){ int j=k/Cin, ci=k-j*Cin; f = W[(co*Cin+ci)*KW+j]; }
        v[u] = __float2bfloat16(f);
    }
    *reinterpret_cast<uint4*>(dst + (size_t)co*Kpad + k0) = *reinterpret_cast<const uint4*>(v);
}

// ---- vectorized im2col [k][t] ----
__global__ void im2col_v8(const float* __restrict__ X, __nv_bfloat16* __restrict__ dst,
                          int C,int T,int Kpad){
    int b = blockIdx.z;
    int idx = blockIdx.x*256+threadIdx.x;
    int T8 = T>>3;
    if (idx >= Kpad*T8) return;
    int k = idx/T8, t8 = (idx - k*T8)<<3;
    __nv_bfloat16 v[8];
    if (k < 3*C){
        int j = k/C, ci = k - j*C;
        const float* src = X + ((size_t)b*C+ci)*T;
        int tb = t8 + j - 1;
#pragma unroll
        for (int u=0;u<8;u++){
            int tt = tb+u;
            v[u] = __float2bfloat16((tt>=0 && tt<T) ? src[tt] : 0.f);
        }
    } else {
#pragma unroll
        for (int u=0;u<8;u++) v[u] = __float2bfloat16(0.f);
    }
    *reinterpret_cast<uint4*>(dst + ((size_t)b*Kpad + k)*T + t8) = *reinterpret_cast<const uint4*>(v);
}

// ---- shared GEMM tile constants ----
#define BM 128
#define BN 128
#define BKT 32
#define AST 40
#define BST 136
#define NSTG 4
#define GSMEM (NSTG*(BM*AST + BKT*BST)*2)

// ======== 128-thread GEMM (4 warps, 64x64 warp tiles) — GEMM1 ========
template <bool RELU>
__global__ void __launch_bounds__(128,2)
gemm128(const __nv_bfloat16* __restrict__ A, size_t aBatch, int lda,
        const __nv_bfloat16* __restrict__ Bm, size_t bBatch, int ldb,
        __nv_bfloat16* __restrict__ Cv, size_t cBatch, int ldc,
        const float* __restrict__ bias, int M, int Kpad, int Mstore){
    extern __shared__ char dsm[];
    __nv_bfloat16* sA = (__nv_bfloat16*)dsm;
    __nv_bfloat16* sB = sA + NSTG*BM*AST;
    const int bz = blockIdx.z;
    A  += (size_t)bz*aBatch;
    Bm += (size_t)bz*bBatch;
    const int m0 = blockIdx.y*BM, n0 = blockIdx.x*BN;
    const int tid = threadIdx.x, lane = tid&31, wid = tid>>5;
    const int wm = wid&1, wn = wid>>1;
    const uint32_t saA = (uint32_t)__cvta_generic_to_shared(sA);
    const uint32_t sbA = (uint32_t)__cvta_generic_to_shared(sB);

    float acc[4][8][4];
#pragma unroll
    for (int i=0;i<4;i++)
#pragma unroll
        for (int j=0;j<8;j++)
#pragma unroll
            for (int q=0;q<4;q++) acc[i][j][q]=0.f;

    const int KT = Kpad/BKT;
    auto loadTiles = [&](int kt,int s){
        int k0 = kt*BKT;
        uint32_t sa = saA + s*(BM*AST*2);
        uint32_t sb = sbA + s*(BKT*BST*2);
#pragma unroll
        for (int i=0;i<4;i++){
            int c = tid+128*i, row = c>>2, cc = (c&3)*8;
            cp16(sa + (row*AST+cc)*2, A + (size_t)(m0+row)*lda + k0 + cc, 16);
        }
#pragma unroll
        for (int i=0;i<4;i++){
            int c = tid+128*i, row = c>>4, cc = (c&15)*8;
            cp16(sb + (row*BST+cc)*2, Bm + (size_t)(k0+row)*ldb + n0 + cc, 16);
        }
    };

    loadTiles(0,0); cpcommit();
    loadTiles(1,1); cpcommit();
    loadTiles(2,2); cpcommit();
    for (int kt=0; kt<KT; kt++){
        int s = kt & 3;
        if (kt >= KT-2) cpwait0(); else cpwait2();
        __syncthreads();
        if (kt+3 < KT){ loadTiles(kt+3, (kt+3)&3); cpcommit(); }
        uint32_t sa = saA + s*(BM*AST*2);
        uint32_t sb = sbA + s*(BKT*BST*2);
#pragma unroll
        for (int ks=0; ks<2; ks++){
            int kk = ks*16;
            uint32_t af[4][4];
#pragma unroll
            for (int i=0;i<4;i++){
                int row = wm*64 + i*16 + (lane&15);
                int col = kk + ((lane>>4)<<3);
                ldsm4(af[i][0],af[i][1],af[i][2],af[i][3], sa + (row*AST+col)*2);
            }
            uint32_t bfr[8][2];
#pragma unroll
            for (int p=0;p<4;p++){
                int row = kk + (lane&15);
                int col = wn*64 + p*16 + ((lane>>4)<<3);
                uint32_t r0,r1,r2,r3;
                ldsm4t(r0,r1,r2,r3, sb + (row*BST+col)*2);
                bfr[2*p][0]=r0; bfr[2*p][1]=r1; bfr[2*p+1][0]=r2; bfr[2*p+1][1]=r3;
            }
#pragma unroll
            for (int i=0;i<4;i++)
#pragma unroll
                for (int j=0;j<8;j++) mma16816(acc[i][j], af[i], bfr[j]);
        }
    }

    const int g = lane>>2, tg = lane&3;
    const size_t cOff = (size_t)bz*cBatch;
#pragma unroll
    for (int i=0;i<4;i++)
#pragma unroll
        for (int j=0;j<8;j++){
            int col = n0 + wn*64 + j*8 + tg*2;
#pragma unroll
            for (int h=0;h<2;h++){
                int r = m0 + wm*64 + i*16 + g + h*8;
                if (r < Mstore){
                    float v0 = acc[i][j][h*2], v1 = acc[i][j][h*2+1];
                    if (r < M){
                        if (bias){ float bb = bias[r]; v0+=bb; v1+=bb; }
                        if (RELU){ v0=fmaxf(v0,0.f); v1=fmaxf(v1,0.f); }
                    } else { v0=0.f; v1=0.f; }
                    __nv_bfloat162 pv; pv.x=__float2bfloat16(v0); pv.y=__float2bfloat16(v1);
                    *reinterpret_cast<__nv_bfloat162*>(Cv + cOff + (size_t)r*ldc + col) = pv;
                }
            }
        }
}

// ======== 256-thread GEMM (8 warps, 32x64 warp tiles) — small layers ========
template <bool RELU, bool TRANSQ>
__global__ void __launch_bounds__(256,2)
gemm256(const __nv_bfloat16* __restrict__ A, size_t aBatch, int lda,
        const __nv_bfloat16* __restrict__ Bm, size_t bBatch, int ldb,
        __nv_bfloat16* __restrict__ Cv, size_t cBatch, int ldc,
        const float* __restrict__ bias, int M, int Kpad, int Mstore,
        float* __restrict__ q2out){
    extern __shared__ char dsm[];
    __nv_bfloat16* sA = (__nv_bfloat16*)dsm;
    __nv_bfloat16* sB = sA + NSTG*BM*AST;
    const int bz = blockIdx.z;
    A  += (size_t)bz*aBatch;
    Bm += (size_t)bz*bBatch;
    const int m0 = blockIdx.y*BM, n0 = blockIdx.x*BN;
    const int tid = threadIdx.x, lane = tid&31, wid = tid>>5;
    const int wm = wid&3, wn = wid>>2;
    const uint32_t saA = (uint32_t)__cvta_generic_to_shared(sA);
    const uint32_t sbA = (uint32_t)__cvta_generic_to_shared(sB);

    float acc[2][8][4];
#pragma unroll
    for (int i=0;i<2;i++)
#pragma unroll
        for (int j=0;j<8;j++){acc[i][j][0]=0;acc[i][j][1]=0;acc[i][j][2]=0;acc[i][j][3]=0;}

    const int KT = Kpad/BKT;
    auto loadTiles = [&](int kt,int s){
        int k0 = kt*BKT;
        uint32_t sa = saA + s*(BM*AST*2);
        uint32_t sb = sbA + s*(BKT*BST*2);
#pragma unroll
        for (int i=0;i<2;i++){
            int c = tid+256*i, row = c>>2, cc = (c&3)*8;
            cp16(sa + (row*AST+cc)*2, A + (size_t)(m0+row)*lda + k0 + cc, 16);
        }
#pragma unroll
        for (int i=0;i<2;i++){
            int c = tid+256*i, row = c>>4, cc = (c&15)*8;
            cp16(sb + (row*BST+cc)*2, Bm + (size_t)(k0+row)*ldb + n0 + cc, 16);
        }
    };

    loadTiles(0,0); cpcommit();
    loadTiles(1,1); cpcommit();
    loadTiles(2,2); cpcommit();
    for (int kt=0; kt<KT; kt++){
        int s = kt & 3;
        if (kt >= KT-2) cpwait0(); else cpwait2();
        __syncthreads();
        if (kt+3 < KT){ loadTiles(kt+3, (kt+3)&3); cpcommit(); }
        uint32_t sa = saA + s*(BM*AST*2);
        uint32_t sb = sbA + s*(BKT*BST*2);
#pragma unroll
        for (int ks=0; ks<2; ks++){
            int kk = ks*16;
            uint32_t af[2][4];
#pragma unroll
            for (int i=0;i<2;i++){
                int row = wm*32 + i*16 + (lane&15);
                int col = kk + ((lane>>4)<<3);
                ldsm4(af[i][0],af[i][1],af[i][2],af[i][3], sa + (row*AST+col)*2);
            }
            uint32_t bfr[8][2];
#pragma unroll
            for (int p=0;p<4;p++){
                int row = kk + (lane&15);
                int col = wn*64 + p*16 + ((lane>>4)<<3);
                uint32_t r0,r1,r2,r3;
                ldsm4t(r0,r1,r2,r3, sb + (row*BST+col)*2);
                bfr[2*p][0]=r0; bfr[2*p][1]=r1; bfr[2*p+1][0]=r2; bfr[2*p+1][1]=r3;
            }
#pragma unroll
            for (int i=0;i<2;i++)
#pragma unroll
                for (int j=0;j<8;j++) mma16816(acc[i][j], af[i], bfr[j]);
        }
    }

    const int g = lane>>2, tg = lane&3;
    if (TRANSQ){
        __syncthreads();
        __nv_bfloat16* sT = (__nv_bfloat16*)dsm;
#pragma unroll
        for (int i=0;i<2;i++)
#pragma unroll
            for (int j=0;j<8;j++){
                int colb = wn*64 + j*8 + tg*2;
#pragma unroll
                for (int q=0;q<4;q++){
                    int h=q>>1, s=q&1;
                    int r = wm*32 + i*16 + g + h*8;
                    float v = acc[i][j][q];
                    if (r < M) v += bias[r]; else v = 0.f;
                    sT[(colb+s)*136 + r] = __float2bfloat16(v);
                }
            }
        __syncthreads();
        if (tid < 128){
            int row = tid;
            size_t t = (size_t)n0 + row;
            const uint4* src = (const uint4*)(sT + row*136);
            uint4* dstp = (uint4*)(Cv + (size_t)bz*cBatch + t*128);
            float ssum = 0.f;
#pragma unroll
            for (int u=0;u<16;u++){
                uint4 w = src[u];
                dstp[u] = w;
                const uint32_t wv[4] = {w.x,w.y,w.z,w.w};
#pragma unroll
                for (int e=0;e<4;e++){
                    float2 f2 = __bfloat1622float2(*reinterpret_cast<const __nv_bfloat162*>(&wv[e]));
                    ssum += f2.x*f2.x + f2.y*f2.y;
                }
            }
            q2out[bz*TT1 + t] = ssum;
        }
        return;
    }

    const size_t cOff = (size_t)bz*cBatch;
#pragma unroll
    for (int i=0;i<2;i++)
#pragma unroll
        for (int j=0;j<8;j++){
            int col = n0 + wn*64 + j*8 + tg*2;
#pragma unroll
            for (int h=0;h<2;h++){
                int r = m0 + wm*32 + i*16 + g + h*8;
                if (r < Mstore){
                    float v0 = acc[i][j][h*2], v1 = acc[i][j][h*2+1];
                    if (r < M){
                        if (bias){ float bb = bias[r]; v0+=bb; v1+=bb; }
                        if (RELU){ v0=fmaxf(v0,0.f); v1=fmaxf(v1,0.f); }
                    } else { v0=0.f; v1=0.f; }
                    __nv_bfloat162 pv; pv.x=__float2bfloat16(v0); pv.y=__float2bfloat16(v1);
                    *reinterpret_cast<__nv_bfloat162*>(Cv + cOff + (size_t)r*ldc + col) = pv;
                }
            }
        }
}

// ---- channel sum-of-squares (K path) ----
__global__ void sumsq_kernel(const __nv_bfloat16* __restrict__ X, float* __restrict__ out,
                             int C,int T,size_t bStride){
    int b = blockIdx.y, t = blockIdx.x*256+threadIdx.x;
    if (t >= T) return;
    const __nv_bfloat16* p = X + (size_t)b*bStride + t;
    float s = 0.f;
    for (int c=0;c<C;c++){ float v = __bfloat162float(p[(size_t)c*T]); s += v*v; }
    out[b*T+t] = s;
}

// ---- fused qk + attention: 64 rows/CTA, 512 threads, staged coalesced outputs ----
#define SQ_E (64*136)
#define SK_E (128*520)
#define PRS 520
#define ATTN_SMEM ((SQ_E+SK_E)*2 + 512*4 + 512*4 + 64*8*4)

template<bool MAXOP>
__device__ __forceinline__ void rowReduce64(float val[2][2], float* sred, int wm,int g,int tg,int wn){
#pragma unroll
    for (int i=0;i<2;i++)
#pragma unroll
        for (int h=0;h<2;h++){
            float v = val[i][h];
            float o = __shfl_xor_sync(0xffffffffu, v, 1);
            v = MAXOP ? fmaxf(v,o) : v+o;
            o = __shfl_xor_sync(0xffffffffu, v, 2);
            v = MAXOP ? fmaxf(v,o) : v+o;
            if (tg==0) sred[(wm*32 + i*16+g+h*8)*8+wn] = v;
        }
    __syncthreads();
#pragma unroll
    for (int i=0;i<2;i++)
#pragma unroll
        for (int h=0;h<2;h++){
            int r = wm*32 + i*16+g+h*8;
            float v = sred[r*8];
#pragma unroll
            for (int w=1;w<8;w++) v = MAXOP ? fmaxf(v,sred[r*8+w]) : v+sred[r*8+w];
            val[i][h]=v;
        }
    __syncthreads();
}

__global__ void __launch_bounds__(512)
qk_attn(const __nv_bfloat16* __restrict__ QT, const __nv_bfloat16* __restrict__ Kb,
        const float* __restrict__ q2, const float* __restrict__ k2,
        const float* __restrict__ prior, const int* __restrict__ mask,
        float* __restrict__ outA, float* __restrict__ outLP){
    extern __shared__ char sm[];
    __nv_bfloat16* sQ = (__nv_bfloat16*)sm;
    __nv_bfloat16* sK = sQ + SQ_E;
    float* sk2  = (float*)(sK + SK_E);
    int*  smask = (int*)(sk2 + 512);
    float* sred = (float*)(smask + 512);
    float* stage = (float*)sK;           // 64*520 fp32 == SK_E*2 bytes exactly

    const int b = blockIdx.y, m0 = blockIdx.x*64;
    const int tid = threadIdx.x, lane = tid&31, wid = tid>>5;
    const int wm = wid>>3, wn = wid&7;
    const int g = lane>>2, tg = lane&3;
    const __nv_bfloat16* Qg = QT + ((size_t)b*TT1 + m0)*128;
    const __nv_bfloat16* Kg = Kb + (size_t)b*128*512;
    const uint32_t sQa = (uint32_t)__cvta_generic_to_shared(sQ);
    const uint32_t sKa = (uint32_t)__cvta_generic_to_shared(sK);

#pragma unroll
    for (int i=0;i<2;i++){
        int c = tid + 512*i, row = c>>4, cc = (c&15)*8;
        cp16(sQa + (row*136+cc)*2, Qg + row*128 + cc, 16);
    }
#pragma unroll
    for (int i=0;i<8;i++){
        int c = tid + 512*i, row = c>>6, cc = (c&63)*8;
        cp16(sKa + (row*520+cc)*2, Kg + row*512 + cc, 16);
    }
    cpcommit();
#pragma unroll
    for (int i=0;i<8;i++){
        int c = tid + 512*i, row = 64 + (c>>6), cc = (c&63)*8;
        cp16(sKa + (row*520+cc)*2, Kg + row*512 + cc, 16);
    }
    cpcommit();
    sk2[tid]   = k2[b*TT2 + tid];
    smask[tid] = mask[b*TT2 + tid];

    float acc[2][8][4];
#pragma unroll
    for (int i=0;i<2;i++)
#pragma unroll
        for (int j=0;j<8;j++){acc[i][j][0]=0;acc[i][j][1]=0;acc[i][j][2]=0;acc[i][j][3]=0;}

    auto computeChunk = [&](int ks0){
#pragma unroll
        for (int ks=0; ks<4; ks++){
            int kk = (ks0+ks)*16;
            uint32_t af[2][4];
#pragma unroll
            for (int i=0;i<2;i++){
                int row = wm*32 + i*16 + (lane&15);
                int col = kk + ((lane>>4)<<3);
                ldsm4(af[i][0],af[i][1],af[i][2],af[i][3], sQa + (row*136+col)*2);
            }
            uint32_t bfr[8][2];
#pragma unroll
            for (int p=0;p<4;p++){
                int row = kk + (lane&15);
                int col = wn*64 + p*16 + ((lane>>4)<<3);
                uint32_t r0,r1,r2,r3;
                ldsm4t(r0,r1,r2,r3, sKa + (row*520+col)*2);
                bfr[2*p][0]=r0; bfr[2*p][1]=r1; bfr[2*p+1][0]=r2; bfr[2*p+1][1]=r3;
            }
#pragma unroll
            for (int i=0;i<2;i++)
#pragma unroll
                for (int j=0;j<8;j++) mma16816(acc[i][j], af[i], bfr[j]);
        }
    };

    cpwait1(); __syncthreads();
    computeChunk(0);
    cpwait0(); __syncthreads();
    computeChunk(4);
    __syncthreads();   // done reading sK — reusable as staging

    // stage prior into 'stage' (64 rows x 512 fp32, stride PRS)
    const size_t rowBase = (size_t)b*TT1 + m0;
    {
        const float* pg = prior + rowBase*TT2;
#pragma unroll
        for (int i=0;i<16;i++){
            int c = tid + 512*i;            // 8192 16B-chunks = 64 rows x 128
            int row = c>>7, cc = c&127;
            cp16(sKa + (row*PRS + cc*4)*4, pg + (size_t)row*TT2 + cc*4, 16);
        }
        cpcommit();
    }

    float q2v[2][2];
#pragma unroll
    for (int i=0;i<2;i++)
#pragma unroll
        for (int h=0;h<2;h++) q2v[i][h] = q2[rowBase + wm*32 + i*16+g+h*8];

#pragma unroll
    for (int i=0;i<2;i++)
#pragma unroll
        for (int j=0;j<8;j++)
#pragma unroll
            for (int q=0;q<4;q++){
                int h = q>>1, s = q&1;
                int col = wn*64 + j*8 + tg*2 + s;
                acc[i][j][q] = -5e-4f*(q2v[i][h] + sk2[col] - 2.f*acc[i][j][q]);
            }

    float mx[2][2] = {{-1e30f,-1e30f},{-1e30f,-1e30f}};
#pragma unroll
    for (int i=0;i<2;i++)
#pragma unroll
        for (int j=0;j<8;j++)
#pragma unroll
            for (int q=0;q<4;q++){ int h=q>>1; mx[i][h] = fmaxf(mx[i][h], acc[i][j][q]); }
    rowReduce64<true>(mx, sred, wm, g, tg, wn);
    float sme[2][2] = {{0,0},{0,0}};
#pragma unroll
    for (int i=0;i<2;i++)
#pragma unroll
        for (int j=0;j<8;j++)
#pragma unroll
            for (int q=0;q<4;q++){ int h=q>>1; sme[i][h] += __expf(acc[i][j][q]-mx[i][h]); }
    rowReduce64<false>(sme, sred, wm, g, tg, wn);
    float lse[2][2];
#pragma unroll
    for (int i=0;i<2;i++)
#pragma unroll
        for (int h=0;h<2;h++) lse[i][h] = mx[i][h] + __logf(sme[i][h]);

    cpwait0(); __syncthreads();   // prior staged

    // lp computed in-place over prior slot (same thread r/w each element)
    float s2[2][2] = {{0,0},{0,0}};
#pragma unroll
    for (int i=0;i<2;i++)
#pragma unroll
        for (int j=0;j<8;j++)
#pragma unroll
            for (int q=0;q<4;q++){
                int h=q>>1, s=q&1;
                int r = wm*32 + i*16+g+h*8, col = wn*64 + j*8 + tg*2 + s;
                float lp = acc[i][j][q] - lse[i][h] + __logf(stage[r*PRS + col] + 1e-8f);
                stage[r*PRS + col] = lp;
                float e = smask[col] ? 0.f : __expf(lp);
                acc[i][j][q] = e;
                s2[i][h] += e;
            }
    rowReduce64<false>(s2, sred, wm, g, tg, wn);   // also orders the stage writes

    // coalesced copy: stage -> outLP (16B/lane)
    {
        float* dst = outLP + rowBase*TT2;
#pragma unroll
        for (int i=0;i<16;i++){
            int c = tid + 512*i;
            int row = c>>7, cc = (c&127)*4;
            *reinterpret_cast<uint4*>(dst + (size_t)row*TT2 + cc) =
                *reinterpret_cast<const uint4*>(stage + row*PRS + cc);
        }
    }
    __syncthreads();   // all copies done before re-staging

    // stage outA = e * inv, then coalesced copy
#pragma unroll
    for (int i=0;i<2;i++)
#pragma unroll
        for (int j=0;j<8;j++)
#pragma unroll
            for (int q=0;q<4;q++){
                int h=q>>1, s=q&1;
                int r = wm*32 + i*16+g+h*8, col = wn*64 + j*8 + tg*2 + s;
                float inv = s2[i][h] > 0.f ? 1.f/s2[i][h] : 0.f;
                stage[r*PRS + col] = acc[i][j][q]*inv;
            }
    __syncthreads();
    {
        float* dst = outA + rowBase*TT2;
#pragma unroll
        for (int i=0;i<16;i++){
            int c = tid + 512*i;
            int row = c>>7, cc = (c&127)*4;
            *reinterpret_cast<uint4*>(dst + (size_t)row*TT2 + cc) =
                *reinterpret_cast<const uint4*>(stage + row*PRS + cc);
        }
    }
}

extern "C" void kernel_launch(void* const* d_in, const int* in_sizes, int n_in,
                              void* d_out, int out_size){
    (void)in_sizes; (void)n_in; (void)out_size;
    const float* queries = (const float*)d_in[0];
    const float* keys    = (const float*)d_in[1];
    const int*   mask    = (const int*)d_in[3];
    const float* prior   = (const float*)d_in[4];
    const float* kW1=(const float*)d_in[5];  const float* kb1=(const float*)d_in[6];
    const float* kW2=(const float*)d_in[7];  const float* kb2=(const float*)d_in[8];
    const float* qW1=(const float*)d_in[9];  const float* qb1=(const float*)d_in[10];
    const float* qW2=(const float*)d_in[11]; const float* qb2=(const float*)d_in[12];
    const float* qW3=(const float*)d_in[13]; const float* qb3=(const float*)d_in[14];

    void *pA1k,*pA2k,*pA1q,*pA2q,*pA3q,*pBk1,*pBq1,*pHk,*pKb,*pHq1,*pHq2,*pQT,*pq2,*pk2;
    cudaGetSymbolAddress(&pA1k,g_A1k); cudaGetSymbolAddress(&pA2k,g_A2k);
    cudaGetSymbolAddress(&pA1q,g_A1q); cudaGetSymbolAddress(&pA2q,g_A2q);
    cudaGetSymbolAddress(&pA3q,g_A3q); cudaGetSymbolAddress(&pBk1,g_Bk1);
    cudaGetSymbolAddress(&pBq1,g_Bq1); cudaGetSymbolAddress(&pHk,g_Hk);
    cudaGetSymbolAddress(&pKb,g_Kb);   cudaGetSymbolAddress(&pHq1,g_Hq1);
    cudaGetSymbolAddress(&pHq2,g_Hq2); cudaGetSymbolAddress(&pQT,g_QT);
    cudaGetSymbolAddress(&pq2,g_q2);   cudaGetSymbolAddress(&pk2,g_k2);

    cudaFuncSetAttribute(gemm128<true>, cudaFuncAttributeMaxDynamicSharedMemorySize, GSMEM);
    cudaFuncSetAttribute(gemm256<false,false>, cudaFuncAttributeMaxDynamicSharedMemorySize, GSMEM);
    cudaFuncSetAttribute(gemm256<true,false>,  cudaFuncAttributeMaxDynamicSharedMemorySize, GSMEM);
    cudaFuncSetAttribute(gemm256<false,true>,  cudaFuncAttributeMaxDynamicSharedMemorySize, GSMEM);
    cudaFuncSetAttribute(qk_attn, cudaFuncAttributeMaxDynamicSharedMemorySize, ATTN_SMEM);

    static cudaStream_t s2 = nullptr;
    static cudaEvent_t eFork = nullptr, eJoin = nullptr;
    if (!s2){
        cudaStreamCreateWithFlags(&s2, cudaStreamNonBlocking);
        cudaEventCreateWithFlags(&eFork, cudaEventDisableTiming);
        cudaEventCreateWithFlags(&eJoin, cudaEventDisableTiming);
    }

    cudaEventRecord(eFork, 0);
    cudaStreamWaitEvent(s2, eFork, 0);

    // --- key path (default stream) ---
    im2col_v8<<<dim3((1536*512/8+255)/256,1,NB),256>>>(keys,(__nv_bfloat16*)pBk1,512,512,1536);
    pack_w8<<<(1024*1536/8+255)/256,256>>>(kW1,(__nv_bfloat16*)pA1k,1024,512,3,1536,1024);
    // --- query path starts on s2 ---
    im2col_v8<<<dim3((320*2048/8+255)/256,1,NB),256,0,s2>>>(queries,(__nv_bfloat16*)pBq1,100,2048,320);
    // launch index 3: dominant GEMM (ncu capture slot)
    gemm128<true><<<dim3(4,8,NB),128,GSMEM>>>(
        (const __nv_bfloat16*)pA1k,0,1536,(const __nv_bfloat16*)pBk1,(size_t)1536*512,512,
        (__nv_bfloat16*)pHk,(size_t)1024*512,512, kb1, 1024,1536,1024);
    pack_w8<<<(128*1024/8+255)/256,256>>>(kW2,(__nv_bfloat16*)pA2k,100,1024,1,1024,128);
    gemm256<false,false><<<dim3(4,1,NB),256,GSMEM>>>(
        (const __nv_bfloat16*)pA2k,0,1024,(const __nv_bfloat16*)pHk,(size_t)1024*512,512,
        (__nv_bfloat16*)pKb,(size_t)128*512,512, kb2, 100,1024,128, nullptr);
    sumsq_kernel<<<dim3(2,NB),256>>>((const __nv_bfloat16*)pKb,(float*)pk2,100,512,(size_t)128*512);

    // --- query path (s2) ---
    pack_w8<<<(224*320/8+255)/256,256,0,s2>>>(qW1,(__nv_bfloat16*)pA1q,200,100,3,320,224);
    pack_w8<<<(128*224/8+255)/256,256,0,s2>>>(qW2,(__nv_bfloat16*)pA2q,100,200,1,224,128);
    pack_w8<<<(128*128/8+255)/256,256,0,s2>>>(qW3,(__nv_bfloat16*)pA3q,100,100,1,128,128);
    gemm256<true,false><<<dim3(16,2,NB),256,GSMEM,s2>>>(
        (const __nv_bfloat16*)pA1q,0,320,(const __nv_bfloat16*)pBq1,(size_t)320*2048,2048,
        (__nv_bfloat16*)pHq1,(size_t)224*2048,2048, qb1, 200,320,224, nullptr);
    gemm256<true,false><<<dim3(16,1,NB),256,GSMEM,s2>>>(
        (const __nv_bfloat16*)pA2q,0,224,(const __nv_bfloat16*)pHq1,(size_t)224*2048,2048,
        (__nv_bfloat16*)pHq2,(size_t)128*2048,2048, qb2, 100,224,128, nullptr);
    gemm256<false,true><<<dim3(16,1,NB),256,GSMEM,s2>>>(
        (const __nv_bfloat16*)pA3q,0,128,(const __nv_bfloat16*)pHq2,(size_t)128*2048,2048,
        (__nv_bfloat16*)pQT,(size_t)2048*128,128, qb3, 100,128,128, (float*)pq2);
    cudaEventRecord(eJoin, s2);
    cudaStreamWaitEvent(0, eJoin, 0);

    // --- join: fused qk + attention ---
    float* outA = (float*)d_out;
    float* outLP = outA + (size_t)NB*TT1*TT2;
    qk_attn<<<dim3(TT1/64,NB),512,ATTN_SMEM>>>(
        (const __nv_bfloat16*)pQT,(const __nv_bfloat16*)pKb,
        (const float*)pq2,(const float*)pk2, prior, mask, outA, outLP);
}